// round 2
// baseline (speedup 1.0000x reference)
#include <cuda_runtime.h>
#include <cstdint>

// ---------------------------------------------------------------------------
// Problem constants
// ---------------------------------------------------------------------------
#define NXX 128
#define VOL (128*128*128)          // 2,097,152
#define NB  2
#define NR  3
#define NF  (NB*NR)
#define LAMBDA 1e-3f
#define EPSI   1e-12f
#define NITER  10
#define INV128 (1.0f/128.0f)

// padded line length for smem FFT buffers (float2 elements)
#define PN 137
__device__ __forceinline__ int padi(int i){ return i + (i>>4); }

// ---------------------------------------------------------------------------
// Static device buffers (no allocations allowed)
// ---------------------------------------------------------------------------
static __device__ float2 d_C0 [NB*VOL];     // complex scratch (B fields)
static __device__ float2 d_tmp[NF*VOL];     // complex scratch (B*R fields)
static __device__ float  d_mT [NF*VOL];     // transposed masks [b][r][vol]
static __device__ float  d_bb [NB*VOL];
static __device__ float  d_xk [NB*VOL];
static __device__ float  d_rr [NB*VOL];
static __device__ float  d_pp [NB*VOL];
static __device__ float  d_Ap [NB*VOL];
static __device__ float2 d_W  [NXX];        // twiddle LUT e^{-2pi i k/128}
static __device__ float  d_rs [NB];
static __device__ float  d_pAp[NB];
static __device__ float  d_rsn[NB];
static __device__ float  d_part[NB*256];

// ---------------------------------------------------------------------------
// complex helpers
// ---------------------------------------------------------------------------
__device__ __forceinline__ float2 c_add(float2 a, float2 b){ return make_float2(a.x+b.x, a.y+b.y); }
__device__ __forceinline__ float2 c_sub(float2 a, float2 b){ return make_float2(a.x-b.x, a.y-b.y); }
__device__ __forceinline__ float2 c_mul(float2 a, float2 b){ return make_float2(a.x*b.x-a.y*b.y, a.x*b.y+a.y*b.x); }

template<int DIR> __device__ __forceinline__ float2 rot90(float2 a){
  // multiply by -i (forward) or +i (inverse)
  return (DIR>0) ? make_float2(a.y,-a.x) : make_float2(-a.y,a.x);
}
template<int DIR> __device__ __forceinline__ float2 twid(const float2* wt, int m){
  float2 w = wt[m];
  return (DIR>0) ? w : make_float2(w.x, -w.y);
}

template<int DIR>
__device__ __forceinline__ void dft8(float2 v[8]){
  const float C = 0.70710678118654752f;
  float2 s04a=c_add(v[0],v[4]), s04s=c_sub(v[0],v[4]);
  float2 s26a=c_add(v[2],v[6]), s26s=c_sub(v[2],v[6]);
  float2 s15a=c_add(v[1],v[5]), s15s=c_sub(v[1],v[5]);
  float2 s37a=c_add(v[3],v[7]), s37s=c_sub(v[3],v[7]);
  float2 E0=c_add(s04a,s26a), E2=c_sub(s04a,s26a);
  float2 r26=rot90<DIR>(s26s);
  float2 E1=c_add(s04s,r26), E3=c_sub(s04s,r26);
  float2 O0=c_add(s15a,s37a), O2=c_sub(s15a,s37a);
  float2 r37=rot90<DIR>(s37s);
  float2 O1=c_add(s15s,r37), O3=c_sub(s15s,r37);
  float2 w1=(DIR>0)?make_float2(C,-C):make_float2(C,C);
  float2 w3=(DIR>0)?make_float2(-C,-C):make_float2(-C,C);
  float2 t;
  v[0]=c_add(E0,O0); v[4]=c_sub(E0,O0);
  t=c_mul(O1,w1);     v[1]=c_add(E1,t); v[5]=c_sub(E1,t);
  t=rot90<DIR>(O2);   v[2]=c_add(E2,t); v[6]=c_sub(E2,t);
  t=c_mul(O3,w3);     v[3]=c_add(E3,t); v[7]=c_sub(E3,t);
}

// Stockham 128-pt FFT, radices 8,8,2. 16 lanes per line.
// Input in bA, output lands in bB. Caller must sync before (data in bA) and
// may read bB right after (function ends with a block sync).
template<int DIR>
__device__ __forceinline__ void fft128_line(float2* bA, float2* bB, const float2* wt, int j){
  float2 v[8];
  // stage 1: Ns=1 R=8, A->B (no twiddles)
  #pragma unroll
  for (int r=0;r<8;r++) v[r] = bA[padi(j + (r<<4))];
  dft8<DIR>(v);
  #pragma unroll
  for (int r=0;r<8;r++) bB[padi((j<<3) + r)] = v[r];
  __syncthreads();
  // stage 2: Ns=8 R=8, B->A
  #pragma unroll
  for (int r=0;r<8;r++) v[r] = bB[padi(j + (r<<4))];
  {
    int t8 = (j & 7) << 1;        // 2*(j%8)
    #pragma unroll
    for (int r=1;r<8;r++) v[r] = c_mul(v[r], twid<DIR>(wt, r*t8));
  }
  dft8<DIR>(v);
  {
    int id2 = ((j>>3)<<6) + (j&7);
    #pragma unroll
    for (int r=0;r<8;r++) bA[padi(id2 + (r<<3))] = v[r];
  }
  __syncthreads();
  // stage 3: Ns=64 R=2, A->B
  #pragma unroll
  for (int k=0;k<4;k++){
    int jj = j + (k<<4);
    float2 a = bA[padi(jj)];
    float2 b = c_mul(bA[padi(jj+64)], twid<DIR>(wt, jj));
    bB[padi(jj)]    = c_add(a,b);
    bB[padi(jj+64)] = c_sub(a,b);
  }
  __syncthreads();
}

// ---------------------------------------------------------------------------
// init kernels
// ---------------------------------------------------------------------------
__global__ void k_initW(){
  int k = threadIdx.x;
  if (k < NXX){
    float s, c;
    sincospif(-(float)k/64.0f, &s, &c);   // angle = -2*pi*k/128
    d_W[k] = make_float2(c, s);
  }
}

__global__ __launch_bounds__(256) void k_transpose_mask(const float* __restrict__ x1){
  int b = blockIdx.y;
  int i = blockIdx.x*256 + threadIdx.x;
  size_t src = (size_t)b*VOL*NR + (size_t)i*NR;
  #pragma unroll
  for (int r=0;r<NR;r++)
    d_mT[((size_t)(b*NR+r))*VOL + i] = x1[src + r];
}

// ---------------------------------------------------------------------------
// FFT pass kernels
// ---------------------------------------------------------------------------

// forward pass along z (contiguous), real input with optional multipliers
__global__ __launch_bounds__(256) void k_fwdz_real(const float* __restrict__ in, int divR,
                                                   const float* __restrict__ m1,
                                                   const float* __restrict__ m2,
                                                   float2* __restrict__ out){
  __shared__ float2 sA[16*PN], sB[16*PN], wt[NXX];
  int tid = threadIdx.x, f = blockIdx.y;
  for (int i=tid;i<NXX;i+=256) wt[i] = d_W[i];
  int fin = divR ? (f/NR) : f;
  const float* pin = in + (size_t)fin*VOL;
  const float* pm1 = m1 ? (m1 + (size_t)f  *VOL) : (const float*)0;
  const float* pm2 = m2 ? (m2 + (size_t)fin*VOL) : (const float*)0;
  size_t gbase = (size_t)blockIdx.x * 16 * 128;
  for (int i=tid;i<2048;i+=256){
    int ln=i>>7, p=i&127;
    size_t g = gbase + (size_t)ln*128 + p;
    float vv = pin[g];
    if (pm1) vv *= pm1[g];
    if (pm2) vv *= pm2[g];
    sA[ln*PN + padi(p)] = make_float2(vv, 0.f);
  }
  __syncthreads();
  int j = tid & 15, lm = tid >> 4;
  fft128_line<1>(sA + lm*PN, sB + lm*PN, wt, j);
  float2* po = out + (size_t)f*VOL;
  for (int i=tid;i<2048;i+=256){
    int ln=i>>7, p=i&127;
    po[gbase + (size_t)ln*128 + p] = sB[ln*PN + padi(p)];
  }
}

// pass along y (stride 128), complex, in-place
template<int DIR>
__global__ __launch_bounds__(256) void k_passy(float2* __restrict__ io, float scale){
  __shared__ float2 sA[16*PN], sB[16*PN], wt[NXX];
  int tid = threadIdx.x, f = blockIdx.y;
  for (int i=tid;i<NXX;i+=256) wt[i] = d_W[i];
  float2* p0 = io + (size_t)f*VOL;
  int l0 = blockIdx.x * 16;                 // lines over (x,z)
  size_t base = (size_t)(l0>>7)*16384 + (l0&127);
  for (int i=tid;i<2048;i+=256){
    int ln=i&15, p=i>>4;
    sA[ln*PN + padi(p)] = p0[base + ln + (size_t)p*128];
  }
  __syncthreads();
  int j = tid & 15, lm = tid >> 4;
  fft128_line<DIR>(sA + lm*PN, sB + lm*PN, wt, j);
  for (int i=tid;i<2048;i+=256){
    int ln=i&15, p=i>>4;
    float2 v = sB[ln*PN + padi(p)];
    p0[base + ln + (size_t)p*128] = make_float2(v.x*scale, v.y*scale);
  }
}

// fused: fwd-x of C0 line, then per r: *S_r, inv-x, store tmp[b,r] (scale 1/128)
__global__ __launch_bounds__(128) void k_spreadx(const float2* __restrict__ cin,
                                                 const float* __restrict__ S,
                                                 float2* __restrict__ outT){
  __shared__ float2 sA[8*PN], sB[8*PN], sF[8*PN], wt[NXX];
  __shared__ float  sS[8*129];
  int tid = threadIdx.x, b = blockIdx.y;
  for (int i=tid;i<NXX;i+=128) wt[i] = d_W[i];
  int l0 = blockIdx.x * 8;                  // lines over (y,z)
  size_t lbase = (size_t)(l0>>7)*128 + (l0&127);
  const float2* pin = cin + (size_t)b*VOL;
  for (int i=tid;i<1024;i+=128){
    int ln=i&7, p=i>>3;
    sA[ln*PN + padi(p)] = pin[lbase + ln + (size_t)p*16384];
  }
  __syncthreads();
  int j = tid & 15, lm = tid >> 4;
  fft128_line<1>(sA + lm*PN, sB + lm*PN, wt, j);
  for (int i=tid;i<8*PN;i+=128) sF[i] = sB[i];
  __syncthreads();
  for (int r=0;r<NR;r++){
    for (int i=tid;i<1024;i+=128){
      int ln=i&7, p=i>>3;
      sS[ln*129+p] = S[(size_t)r*VOL + lbase + ln + (size_t)p*16384];
    }
    __syncthreads();
    for (int i=tid;i<1024;i+=128){
      int ln=i&7, p=i>>3;
      float s = sS[ln*129+p];
      float2 fv = sF[ln*PN + padi(p)];
      sA[ln*PN + padi(p)] = make_float2(fv.x*s, fv.y*s);
    }
    __syncthreads();
    fft128_line<-1>(sA + lm*PN, sB + lm*PN, wt, j);
    float2* po = outT + (size_t)(b*NR+r)*VOL;
    for (int i=tid;i<1024;i+=128){
      int ln=i&7, p=i>>3;
      float2 v = sB[ln*PN + padi(p)];
      po[lbase + ln + (size_t)p*16384] = make_float2(v.x*INV128, v.y*INV128);
    }
    __syncthreads();
  }
}

// fused z: inv-z, real*(1/128)*mask, fwd-z (in-place on tmp)
__global__ __launch_bounds__(256) void k_zfuse(float2* __restrict__ io,
                                               const float* __restrict__ mask){
  __shared__ float2 sA[16*PN], sB[16*PN], wt[NXX];
  __shared__ float  sM[16*129];
  int tid = threadIdx.x, f = blockIdx.y;
  for (int i=tid;i<NXX;i+=256) wt[i] = d_W[i];
  float2* p0 = io + (size_t)f*VOL;
  const float* pm = mask + (size_t)f*VOL;
  size_t gbase = (size_t)blockIdx.x * 16 * 128;
  for (int i=tid;i<2048;i+=256){
    int ln=i>>7, p=i&127;
    sA[ln*PN + padi(p)] = p0[gbase + (size_t)ln*128 + p];
    sM[ln*129 + p]      = pm[gbase + (size_t)ln*128 + p];
  }
  __syncthreads();
  int j = tid & 15, lm = tid >> 4;
  fft128_line<-1>(sA + lm*PN, sB + lm*PN, wt, j);
  for (int i=tid;i<2048;i+=256){
    int ln=i>>7, p=i&127;
    sA[ln*PN + padi(p)] = make_float2(sB[ln*PN + padi(p)].x * INV128 * sM[ln*129+p], 0.f);
  }
  __syncthreads();
  fft128_line<1>(sA + lm*PN, sB + lm*PN, wt, j);
  for (int i=tid;i<2048;i+=256){
    int ln=i>>7, p=i&127;
    p0[gbase + (size_t)ln*128 + p] = sB[ln*PN + padi(p)];
  }
}

// fused gather: for r: fwd-x(tmp[b,r]) * S_r, sum; inv-x; store C0[b] (scale 1/128)
__global__ __launch_bounds__(128) void k_gatherx(const float2* __restrict__ tmp,
                                                 const float* __restrict__ S,
                                                 float2* __restrict__ cout){
  __shared__ float2 sA[8*PN], sB[8*PN], sF[8*PN], wt[NXX];
  __shared__ float  sS[8*129];
  int tid = threadIdx.x, b = blockIdx.y;
  for (int i=tid;i<NXX;i+=128) wt[i] = d_W[i];
  int l0 = blockIdx.x * 8;
  size_t lbase = (size_t)(l0>>7)*128 + (l0&127);
  for (int i=tid;i<8*PN;i+=128) sF[i] = make_float2(0.f,0.f);
  int j = tid & 15, lm = tid >> 4;
  for (int r=0;r<NR;r++){
    const float2* pin = tmp + (size_t)(b*NR+r)*VOL;
    for (int i=tid;i<1024;i+=128){
      int ln=i&7, p=i>>3;
      sA[ln*PN + padi(p)] = pin[lbase + ln + (size_t)p*16384];
    }
    __syncthreads();
    fft128_line<1>(sA + lm*PN, sB + lm*PN, wt, j);
    for (int i=tid;i<1024;i+=128){
      int ln=i&7, p=i>>3;
      sS[ln*129+p] = S[(size_t)r*VOL + lbase + ln + (size_t)p*16384];
    }
    __syncthreads();
    for (int i=tid;i<1024;i+=128){
      int ln=i&7, p=i>>3;
      float s = sS[ln*129+p];
      float2 v = sB[ln*PN + padi(p)];
      float2 f = sF[ln*PN + padi(p)];
      sF[ln*PN + padi(p)] = make_float2(f.x + v.x*s, f.y + v.y*s);
    }
    __syncthreads();
  }
  for (int i=tid;i<8*PN;i+=128) sA[i] = sF[i];
  __syncthreads();
  fft128_line<-1>(sA + lm*PN, sB + lm*PN, wt, j);
  float2* po = cout + (size_t)b*VOL;
  for (int i=tid;i<1024;i+=128){
    int ln=i&7, p=i>>3;
    float2 v = sB[ln*PN + padi(p)];
    po[lbase + ln + (size_t)p*16384] = make_float2(v.x*INV128, v.y*INV128);
  }
}

// inv-z, output real (scale 1/128), optional + lam * vadd
__global__ __launch_bounds__(256) void k_invz_real(const float2* __restrict__ cin,
                                                   float* __restrict__ outR,
                                                   const float* __restrict__ vadd,
                                                   float lam){
  __shared__ float2 sA[16*PN], sB[16*PN], wt[NXX];
  int tid = threadIdx.x, f = blockIdx.y;
  for (int i=tid;i<NXX;i+=256) wt[i] = d_W[i];
  const float2* p0 = cin + (size_t)f*VOL;
  float* po = outR + (size_t)f*VOL;
  const float* pv = vadd ? (vadd + (size_t)f*VOL) : (const float*)0;
  size_t gbase = (size_t)blockIdx.x * 16 * 128;
  for (int i=tid;i<2048;i+=256){
    int ln=i>>7, p=i&127;
    sA[ln*PN + padi(p)] = p0[gbase + (size_t)ln*128 + p];
  }
  __syncthreads();
  int j = tid & 15, lm = tid >> 4;
  fft128_line<-1>(sA + lm*PN, sB + lm*PN, wt, j);
  for (int i=tid;i<2048;i+=256){
    int ln=i>>7, p=i&127;
    size_t g = gbase + (size_t)ln*128 + p;
    float v = sB[ln*PN + padi(p)].x * INV128;
    if (pv) v += lam * pv[g];
    po[g] = v;
  }
}

// ---------------------------------------------------------------------------
// CG scalar machinery (deterministic two-stage reductions)
// ---------------------------------------------------------------------------
__device__ __forceinline__ float blk_reduce(float v, float* sm){
  int t = threadIdx.x;
  sm[t] = v; __syncthreads();
  for (int s=128; s>0; s>>=1){ if (t<s) sm[t]+=sm[t+s]; __syncthreads(); }
  return sm[0];
}

__global__ __launch_bounds__(256) void k_dot(const float* __restrict__ a,
                                             const float* __restrict__ b,
                                             float* __restrict__ part){
  __shared__ float sm[256];
  int bb = blockIdx.y;
  const float* pa = a + (size_t)bb*VOL;
  const float* pb = b + (size_t)bb*VOL;
  float s = 0.f;
  for (int i=blockIdx.x*256+threadIdx.x; i<VOL; i+=256*256) s += pa[i]*pb[i];
  float tot = blk_reduce(s, sm);
  if (threadIdx.x==0) part[bb*256 + blockIdx.x] = tot;
}

__global__ void k_fin(const float* __restrict__ part, float* __restrict__ out){
  __shared__ float sm[256];
  int b = blockIdx.x;
  float tot = blk_reduce(part[b*256 + threadIdx.x], sm);
  if (threadIdx.x==0) out[b] = tot;
}

__global__ __launch_bounds__(256) void k_init_r(const float* __restrict__ bvec,
                                                const float* __restrict__ Ap,
                                                float* __restrict__ rr,
                                                float* __restrict__ pp,
                                                float* __restrict__ part){
  __shared__ float sm[256];
  int bb = blockIdx.y;
  size_t off = (size_t)bb*VOL;
  float s = 0.f;
  for (int i=blockIdx.x*256+threadIdx.x; i<VOL; i+=256*256){
    float v = bvec[off+i] - Ap[off+i];
    rr[off+i] = v; pp[off+i] = v;
    s += v*v;
  }
  float tot = blk_reduce(s, sm);
  if (threadIdx.x==0) part[bb*256 + blockIdx.x] = tot;
}

__global__ __launch_bounds__(256) void k_update1(float* __restrict__ xk,
                                                 float* __restrict__ rr,
                                                 const float* __restrict__ pp,
                                                 const float* __restrict__ Ap,
                                                 const float* __restrict__ rs,
                                                 const float* __restrict__ pAp,
                                                 float* __restrict__ part){
  __shared__ float sm[256];
  int bb = blockIdx.y;
  float alpha = rs[bb] / (pAp[bb] + EPSI);
  size_t off = (size_t)bb*VOL;
  float s = 0.f;
  for (int i=blockIdx.x*256+threadIdx.x; i<VOL; i+=256*256){
    xk[off+i] += alpha * pp[off+i];
    float rn = rr[off+i] - alpha * Ap[off+i];
    rr[off+i] = rn;
    s += rn*rn;
  }
  float tot = blk_reduce(s, sm);
  if (threadIdx.x==0) part[bb*256 + blockIdx.x] = tot;
}

__global__ __launch_bounds__(256) void k_update2(float* __restrict__ pp,
                                                 const float* __restrict__ rr,
                                                 const float* __restrict__ rs,
                                                 const float* __restrict__ rsn){
  int bb = blockIdx.y;
  float beta = rsn[bb] / (rs[bb] + EPSI);
  size_t off = (size_t)bb*VOL;
  for (int i=blockIdx.x*256+threadIdx.x; i<VOL; i+=256*256)
    pp[off+i] = rr[off+i] + beta * pp[off+i];
}

__global__ void k_rscopy(float* rs, const float* rsn){
  if (threadIdx.x < NB) rs[threadIdx.x] = rsn[threadIdx.x];
}

// ---------------------------------------------------------------------------
// Host side
// ---------------------------------------------------------------------------
static void applyA(const float* vin, float* vout, const float* smv,
                   float2* pC0, float2* pTmp, const float* pMT){
  dim3 gB (1024, NB),  gBR(1024, NF), gS(2048, NB);
  k_fwdz_real<<<gB, 256>>>(vin, 0, 0, 0, pC0);
  k_passy<1><<<gB, 256>>>(pC0, 1.f);
  k_spreadx<<<gS, 128>>>(pC0, smv, pTmp);
  k_passy<-1><<<gBR, 256>>>(pTmp, INV128);
  k_zfuse<<<gBR, 256>>>(pTmp, pMT);
  k_passy<1><<<gBR, 256>>>(pTmp, 1.f);
  k_gatherx<<<gS, 128>>>(pTmp, smv, pC0);
  k_passy<-1><<<gB, 256>>>(pC0, INV128);
  k_invz_real<<<gB, 256>>>(pC0, vout, vin, LAMBDA);
}

extern "C" void kernel_launch(void* const* d_in, const int* in_sizes, int n_in,
                              void* d_out, int out_size){
  const float* x      = (const float*)d_in[0];   // [B,V]
  const float* x1     = (const float*)d_in[1];   // [B,V,R]
  const float* x3     = (const float*)d_in[2];   // [B,V]
  const float* init_x = (const float*)d_in[3];   // [B,V]
  const float* smv    = (const float*)d_in[4];   // [R,V]
  float* out = (float*)d_out;

  float2 *pC0, *pTmp;
  float *pMT, *pB, *pXk, *pR, *pP, *pAp, *pRs, *pPAp, *pRsn, *pPart;
  cudaGetSymbolAddress((void**)&pC0,  d_C0);
  cudaGetSymbolAddress((void**)&pTmp, d_tmp);
  cudaGetSymbolAddress((void**)&pMT,  d_mT);
  cudaGetSymbolAddress((void**)&pB,   d_bb);
  cudaGetSymbolAddress((void**)&pXk,  d_xk);
  cudaGetSymbolAddress((void**)&pR,   d_rr);
  cudaGetSymbolAddress((void**)&pP,   d_pp);
  cudaGetSymbolAddress((void**)&pAp,  d_Ap);
  cudaGetSymbolAddress((void**)&pRs,  d_rs);
  cudaGetSymbolAddress((void**)&pPAp, d_pAp);
  cudaGetSymbolAddress((void**)&pRsn, d_rsn);
  cudaGetSymbolAddress((void**)&pPart,d_part);

  k_initW<<<1,128>>>();
  k_transpose_mask<<<dim3(VOL/256, NB), 256>>>(x1);
  cudaMemcpyAsync(pXk, init_x, (size_t)NB*VOL*sizeof(float), cudaMemcpyDeviceToDevice);

  // b = smv_adj( m * (w3 * x) )
  {
    dim3 gBR(1024, NF), gB(1024, NB), gS(2048, NB);
    k_fwdz_real<<<gBR, 256>>>(x, 1, pMT, x3, pTmp);
    k_passy<1><<<gBR, 256>>>(pTmp, 1.f);
    k_gatherx<<<gS, 128>>>(pTmp, smv, pC0);
    k_passy<-1><<<gB, 256>>>(pC0, INV128);
    k_invz_real<<<gB, 256>>>(pC0, pB, 0, 0.f);
  }

  // r0 = b - A(x0); p = r0; rs = <r0,r0>
  applyA(pXk, pAp, smv, pC0, pTmp, pMT);
  k_init_r<<<dim3(256, NB), 256>>>(pB, pAp, pR, pP, pPart);
  k_fin<<<NB, 256>>>(pPart, pRs);

  for (int it=0; it<NITER; ++it){
    applyA(pP, pAp, smv, pC0, pTmp, pMT);
    k_dot<<<dim3(256, NB), 256>>>(pP, pAp, pPart);
    k_fin<<<NB, 256>>>(pPart, pPAp);
    k_update1<<<dim3(256, NB), 256>>>(pXk, pR, pP, pAp, pRs, pPAp, pPart);
    k_fin<<<NB, 256>>>(pPart, pRsn);
    k_update2<<<dim3(256, NB), 256>>>(pP, pR, pRs, pRsn);
    k_rscopy<<<1, 32>>>(pRs, pRsn);
  }

  cudaMemcpyAsync(out, pXk, (size_t)NB*VOL*sizeof(float), cudaMemcpyDeviceToDevice);
}

// round 3
// speedup vs baseline: 1.9306x; 1.9306x over previous
#include <cuda_runtime.h>
#include <cstdint>

// ---------------------------------------------------------------------------
// Problem constants
// ---------------------------------------------------------------------------
#define NXX 128
#define VOL (128*128*128)          // 2,097,152
#define NB  2
#define NR  3
#define LAMBDA 1e-3f
#define EPSI   1e-12f
#define NITER  10
#define INV128 (1.0f/128.0f)

// padded line length for smem FFT buffers (float2 elements)
#define PN 137
__device__ __forceinline__ int padi(int i){ return i + (i>>4); }

// ---------------------------------------------------------------------------
// Static device buffers (no allocations allowed).
// All CG vectors are PACKED: float2 z with z.x = batch0, z.y = batch1.
// ---------------------------------------------------------------------------
static __device__ float2 d_C0 [VOL];        // complex scratch (1 packed field)
static __device__ float2 d_tmp[NR*VOL];     // complex scratch (R packed fields)
static __device__ float  d_Se [NR*VOL];     // symmetrized SMV kernels
static __device__ uchar2 d_m8 [NR*VOL];     // masks packed (b0,b1) per radius
static __device__ float2 d_bb [VOL];
static __device__ float2 d_xk [VOL];
static __device__ float2 d_rr [VOL];
static __device__ float2 d_pp [VOL];
static __device__ float2 d_Ap [VOL];
static __device__ float2 d_W  [NXX];        // twiddle LUT e^{-2pi i k/128}
static __device__ float  d_rs [NB];
static __device__ float  d_pAp[NB];
static __device__ float  d_rsn[NB];
static __device__ float  d_part[NB*1024];

// ---------------------------------------------------------------------------
// complex helpers
// ---------------------------------------------------------------------------
__device__ __forceinline__ float2 c_add(float2 a, float2 b){ return make_float2(a.x+b.x, a.y+b.y); }
__device__ __forceinline__ float2 c_sub(float2 a, float2 b){ return make_float2(a.x-b.x, a.y-b.y); }
__device__ __forceinline__ float2 c_mul(float2 a, float2 b){ return make_float2(a.x*b.x-a.y*b.y, a.x*b.y+a.y*b.x); }

template<int DIR> __device__ __forceinline__ float2 rot90(float2 a){
  return (DIR>0) ? make_float2(a.y,-a.x) : make_float2(-a.y,a.x);
}
template<int DIR> __device__ __forceinline__ float2 twid(const float2* wt, int m){
  float2 w = wt[m];
  return (DIR>0) ? w : make_float2(w.x, -w.y);
}

template<int DIR>
__device__ __forceinline__ void dft8(float2 v[8]){
  const float C = 0.70710678118654752f;
  float2 s04a=c_add(v[0],v[4]), s04s=c_sub(v[0],v[4]);
  float2 s26a=c_add(v[2],v[6]), s26s=c_sub(v[2],v[6]);
  float2 s15a=c_add(v[1],v[5]), s15s=c_sub(v[1],v[5]);
  float2 s37a=c_add(v[3],v[7]), s37s=c_sub(v[3],v[7]);
  float2 E0=c_add(s04a,s26a), E2=c_sub(s04a,s26a);
  float2 r26=rot90<DIR>(s26s);
  float2 E1=c_add(s04s,r26), E3=c_sub(s04s,r26);
  float2 O0=c_add(s15a,s37a), O2=c_sub(s15a,s37a);
  float2 r37=rot90<DIR>(s37s);
  float2 O1=c_add(s15s,r37), O3=c_sub(s15s,r37);
  float2 w1=(DIR>0)?make_float2(C,-C):make_float2(C,C);
  float2 w3=(DIR>0)?make_float2(-C,-C):make_float2(-C,C);
  float2 t;
  v[0]=c_add(E0,O0); v[4]=c_sub(E0,O0);
  t=c_mul(O1,w1);     v[1]=c_add(E1,t); v[5]=c_sub(E1,t);
  t=rot90<DIR>(O2);   v[2]=c_add(E2,t); v[6]=c_sub(E2,t);
  t=c_mul(O3,w3);     v[3]=c_add(E3,t); v[7]=c_sub(E3,t);
}

// Stockham 128-pt FFT, radices 8,8,2. 16 lanes per line.
template<int DIR>
__device__ __forceinline__ void fft128_line(float2* bA, float2* bB, const float2* wt, int j){
  float2 v[8];
  #pragma unroll
  for (int r=0;r<8;r++) v[r] = bA[padi(j + (r<<4))];
  dft8<DIR>(v);
  #pragma unroll
  for (int r=0;r<8;r++) bB[padi((j<<3) + r)] = v[r];
  __syncthreads();
  #pragma unroll
  for (int r=0;r<8;r++) v[r] = bB[padi(j + (r<<4))];
  {
    int t8 = (j & 7) << 1;
    #pragma unroll
    for (int r=1;r<8;r++) v[r] = c_mul(v[r], twid<DIR>(wt, r*t8));
  }
  dft8<DIR>(v);
  {
    int id2 = ((j>>3)<<6) + (j&7);
    #pragma unroll
    for (int r=0;r<8;r++) bA[padi(id2 + (r<<3))] = v[r];
  }
  __syncthreads();
  #pragma unroll
  for (int k=0;k<4;k++){
    int jj = j + (k<<4);
    float2 a = bA[padi(jj)];
    float2 b = c_mul(bA[padi(jj+64)], twid<DIR>(wt, jj));
    bB[padi(jj)]    = c_add(a,b);
    bB[padi(jj+64)] = c_sub(a,b);
  }
  __syncthreads();
}

// ---------------------------------------------------------------------------
// init kernels
// ---------------------------------------------------------------------------
__global__ void k_initW(){
  int k = threadIdx.x;
  if (k < NXX){
    float s, c;
    sincospif(-(float)k/64.0f, &s, &c);
    d_W[k] = make_float2(c, s);
  }
}

// pack xk (init), wx = w3*x into d_rr (temp), masks into uchar2
__global__ __launch_bounds__(256) void k_prep(const float* __restrict__ x,
                                              const float* __restrict__ x1,
                                              const float* __restrict__ x3,
                                              const float* __restrict__ ix){
  int i = blockIdx.x*256 + threadIdx.x;
  d_xk[i] = make_float2(ix[i], ix[VOL+i]);
  d_rr[i] = make_float2(x[i]*x3[i], x[VOL+i]*x3[VOL+i]);
  #pragma unroll
  for (int r=0;r<NR;r++){
    float m0 = x1[(size_t)i*NR + r];
    float m1 = x1[(size_t)VOL*NR + (size_t)i*NR + r];
    d_m8[(size_t)r*VOL + i] = make_uchar2(m0 != 0.f, m1 != 0.f);
  }
}

// Se[r][k] = 0.5*(S[r][k] + S[r][-k])
__global__ __launch_bounds__(256) void k_prepSe(const float* __restrict__ smv){
  int r = blockIdx.y;
  int i = blockIdx.x*256 + threadIdx.x;
  int h = i >> 14, w = (i >> 7) & 127, dd = i & 127;
  int ni = (((128-h)&127) << 14) | (((128-w)&127) << 7) | ((128-dd)&127);
  d_Se[(size_t)r*VOL + i] = 0.5f*(smv[(size_t)r*VOL + i] + smv[(size_t)r*VOL + ni]);
}

// ---------------------------------------------------------------------------
// FFT pass kernels (all operate on packed complex fields)
// ---------------------------------------------------------------------------

// forward z-pass (contiguous). in: one packed field. Optional per-radius mask
// (blockIdx.y = radius). out += f*VOL.
__global__ __launch_bounds__(256) void k_fwdz(const float2* __restrict__ in,
                                              const uchar2* __restrict__ mask,
                                              float2* __restrict__ out){
  __shared__ float2 sA[16*PN], sB[16*PN], wt[NXX];
  int tid = threadIdx.x, f = blockIdx.y;
  for (int i=tid;i<NXX;i+=256) wt[i] = d_W[i];
  const uchar2* pm = mask ? (mask + (size_t)f*VOL) : (const uchar2*)0;
  size_t gbase = (size_t)blockIdx.x * 2048;
  for (int i=tid;i<2048;i+=256){
    int ln=i>>7, p=i&127;
    size_t g = gbase + (size_t)ln*128 + p;
    float2 vv = in[g];
    if (pm){ uchar2 m = pm[g]; vv.x *= (float)m.x; vv.y *= (float)m.y; }
    sA[ln*PN + padi(p)] = vv;
  }
  __syncthreads();
  int j = tid & 15, lm = tid >> 4;
  fft128_line<1>(sA + lm*PN, sB + lm*PN, wt, j);
  float2* po = out + (size_t)f*VOL;
  for (int i=tid;i<2048;i+=256){
    int ln=i>>7, p=i&127;
    po[gbase + (size_t)ln*128 + p] = sB[ln*PN + padi(p)];
  }
}

// pass along y (stride 128), complex, in-place; blockIdx.y = field
template<int DIR>
__global__ __launch_bounds__(256) void k_passy(float2* __restrict__ io, float scale){
  __shared__ float2 sA[16*PN], sB[16*PN], wt[NXX];
  int tid = threadIdx.x, f = blockIdx.y;
  for (int i=tid;i<NXX;i+=256) wt[i] = d_W[i];
  float2* p0 = io + (size_t)f*VOL;
  int l0 = blockIdx.x * 16;                 // lines over (x,z)
  size_t base = (size_t)(l0>>7)*16384 + (l0&127);
  for (int i=tid;i<2048;i+=256){
    int ln=i&15, p=i>>4;
    sA[ln*PN + padi(p)] = p0[base + ln + (size_t)p*128];
  }
  __syncthreads();
  int j = tid & 15, lm = tid >> 4;
  fft128_line<DIR>(sA + lm*PN, sB + lm*PN, wt, j);
  for (int i=tid;i<2048;i+=256){
    int ln=i&15, p=i>>4;
    float2 v = sB[ln*PN + padi(p)];
    p0[base + ln + (size_t)p*128] = make_float2(v.x*scale, v.y*scale);
  }
}

// fused: fwd-x of C0 line, then per r: *Se_r, inv-x, store tmp[r] (scale 1/128)
__global__ __launch_bounds__(128) void k_spreadx(const float2* __restrict__ cin,
                                                 const float* __restrict__ S,
                                                 float2* __restrict__ outT){
  __shared__ float2 sA[8*PN], sB[8*PN], sF[8*PN], wt[NXX];
  __shared__ float  sS[8*129];
  int tid = threadIdx.x;
  for (int i=tid;i<NXX;i+=128) wt[i] = d_W[i];
  int l0 = blockIdx.x * 8;                  // lines over (y,z)
  for (int i=tid;i<1024;i+=128){
    int ln=i&7, p=i>>3;
    sA[ln*PN + padi(p)] = cin[l0 + ln + (size_t)p*16384];
  }
  __syncthreads();
  int j = tid & 15, lm = tid >> 4;
  fft128_line<1>(sA + lm*PN, sB + lm*PN, wt, j);
  for (int i=tid;i<8*PN;i+=128) sF[i] = sB[i];
  __syncthreads();
  for (int r=0;r<NR;r++){
    for (int i=tid;i<1024;i+=128){
      int ln=i&7, p=i>>3;
      sS[ln*129+p] = S[(size_t)r*VOL + l0 + ln + (size_t)p*16384];
    }
    __syncthreads();
    for (int i=tid;i<1024;i+=128){
      int ln=i&7, p=i>>3;
      float s = sS[ln*129+p];
      float2 fv = sF[ln*PN + padi(p)];
      sA[ln*PN + padi(p)] = make_float2(fv.x*s, fv.y*s);
    }
    __syncthreads();
    fft128_line<-1>(sA + lm*PN, sB + lm*PN, wt, j);
    float2* po = outT + (size_t)r*VOL;
    for (int i=tid;i<1024;i+=128){
      int ln=i&7, p=i>>3;
      float2 v = sB[ln*PN + padi(p)];
      po[l0 + ln + (size_t)p*16384] = make_float2(v.x*INV128, v.y*INV128);
    }
    __syncthreads();
  }
}

// fused z: inv-z, *(1/128)*masks (per component/batch), fwd-z (in-place on tmp[r])
__global__ __launch_bounds__(256) void k_zfuse(float2* __restrict__ io,
                                               const uchar2* __restrict__ mask){
  __shared__ float2 sA[16*PN], sB[16*PN], wt[NXX];
  __shared__ uchar2 sM[16*129];
  int tid = threadIdx.x, f = blockIdx.y;
  for (int i=tid;i<NXX;i+=256) wt[i] = d_W[i];
  float2* p0 = io + (size_t)f*VOL;
  const uchar2* pm = mask + (size_t)f*VOL;
  size_t gbase = (size_t)blockIdx.x * 2048;
  for (int i=tid;i<2048;i+=256){
    int ln=i>>7, p=i&127;
    sA[ln*PN + padi(p)] = p0[gbase + (size_t)ln*128 + p];
    sM[ln*129 + p]      = pm[gbase + (size_t)ln*128 + p];
  }
  __syncthreads();
  int j = tid & 15, lm = tid >> 4;
  fft128_line<-1>(sA + lm*PN, sB + lm*PN, wt, j);
  for (int i=tid;i<2048;i+=256){
    int ln=i>>7, p=i&127;
    float2 v = sB[ln*PN + padi(p)];
    uchar2 m = sM[ln*129+p];
    sA[ln*PN + padi(p)] = make_float2(v.x * INV128 * (float)m.x,
                                      v.y * INV128 * (float)m.y);
  }
  __syncthreads();
  fft128_line<1>(sA + lm*PN, sB + lm*PN, wt, j);
  for (int i=tid;i<2048;i+=256){
    int ln=i>>7, p=i&127;
    p0[gbase + (size_t)ln*128 + p] = sB[ln*PN + padi(p)];
  }
}

// fused gather: for r: fwd-x(tmp[r]) * Se_r, sum; inv-x; store C0 (scale 1/128)
__global__ __launch_bounds__(128) void k_gatherx(const float2* __restrict__ tmp,
                                                 const float* __restrict__ S,
                                                 float2* __restrict__ cout){
  __shared__ float2 sA[8*PN], sB[8*PN], sF[8*PN], wt[NXX];
  __shared__ float  sS[8*129];
  int tid = threadIdx.x;
  for (int i=tid;i<NXX;i+=128) wt[i] = d_W[i];
  int l0 = blockIdx.x * 8;
  for (int i=tid;i<8*PN;i+=128) sF[i] = make_float2(0.f,0.f);
  int j = tid & 15, lm = tid >> 4;
  for (int r=0;r<NR;r++){
    const float2* pin = tmp + (size_t)r*VOL;
    for (int i=tid;i<1024;i+=128){
      int ln=i&7, p=i>>3;
      sA[ln*PN + padi(p)] = pin[l0 + ln + (size_t)p*16384];
    }
    __syncthreads();
    fft128_line<1>(sA + lm*PN, sB + lm*PN, wt, j);
    for (int i=tid;i<1024;i+=128){
      int ln=i&7, p=i>>3;
      sS[ln*129+p] = S[(size_t)r*VOL + l0 + ln + (size_t)p*16384];
    }
    __syncthreads();
    for (int i=tid;i<1024;i+=128){
      int ln=i&7, p=i>>3;
      float s = sS[ln*129+p];
      float2 v = sB[ln*PN + padi(p)];
      float2 f = sF[ln*PN + padi(p)];
      sF[ln*PN + padi(p)] = make_float2(f.x + v.x*s, f.y + v.y*s);
    }
    __syncthreads();
  }
  for (int i=tid;i<8*PN;i+=128) sA[i] = sF[i];
  __syncthreads();
  fft128_line<-1>(sA + lm*PN, sB + lm*PN, wt, j);
  for (int i=tid;i<1024;i+=128){
    int ln=i&7, p=i>>3;
    float2 v = sB[l0 >= 0 ? (lm*0 + (i&7)*PN + padi(i>>3)) : 0];  // (placeholder removed below)
    (void)v;
    float2 vv = sB[(i&7)*PN + padi(i>>3)];
    cout[l0 + (i&7) + (size_t)(i>>3)*16384] = make_float2(vv.x*INV128, vv.y*INV128);
  }
}

// inv-z + Ap = re/im*(1/128) + lam*p, fused partial dot(p,Ap) per batch
__global__ __launch_bounds__(256) void k_invz_ap(const float2* __restrict__ cin,
                                                 float2* __restrict__ outAp,
                                                 const float2* __restrict__ pvec,
                                                 float lam,
                                                 float* __restrict__ part){
  __shared__ float2 sA[16*PN], sB[16*PN], wt[NXX];
  __shared__ float sm0[256], sm1[256];
  int tid = threadIdx.x;
  for (int i=tid;i<NXX;i+=256) wt[i] = d_W[i];
  size_t gbase = (size_t)blockIdx.x * 2048;
  for (int i=tid;i<2048;i+=256){
    int ln=i>>7, p=i&127;
    sA[ln*PN + padi(p)] = cin[gbase + (size_t)ln*128 + p];
  }
  __syncthreads();
  int j = tid & 15, lm = tid >> 4;
  fft128_line<-1>(sA + lm*PN, sB + lm*PN, wt, j);
  float s0 = 0.f, s1 = 0.f;
  for (int i=tid;i<2048;i+=256){
    int ln=i>>7, p=i&127;
    size_t g = gbase + (size_t)ln*128 + p;
    float2 v = sB[ln*PN + padi(p)];
    float2 ap = make_float2(v.x*INV128, v.y*INV128);
    if (pvec){
      float2 pv = pvec[g];
      ap.x += lam*pv.x; ap.y += lam*pv.y;
      s0 += pv.x*ap.x;  s1 += pv.y*ap.y;
    }
    outAp[g] = ap;
  }
  if (part){
    sm0[tid]=s0; sm1[tid]=s1; __syncthreads();
    for (int s=128;s>0;s>>=1){ if (tid<s){ sm0[tid]+=sm0[tid+s]; sm1[tid]+=sm1[tid+s]; } __syncthreads(); }
    if (tid==0){ part[blockIdx.x]=sm0[0]; part[1024+blockIdx.x]=sm1[0]; }
  }
}

// ---------------------------------------------------------------------------
// CG scalar machinery (deterministic two-stage reductions, packed)
// ---------------------------------------------------------------------------
__global__ void k_fin(const float* __restrict__ part, float* __restrict__ out, int n){
  __shared__ float sm[256];
  int b = blockIdx.x, t = threadIdx.x;
  float s = 0.f;
  for (int jj=t; jj<n; jj+=256) s += part[b*1024 + jj];
  sm[t]=s; __syncthreads();
  for (int st=128; st>0; st>>=1){ if (t<st) sm[t]+=sm[t+st]; __syncthreads(); }
  if (t==0) out[b] = sm[0];
}

__global__ __launch_bounds__(256) void k_init_r(float* __restrict__ part){
  __shared__ float sm0[256], sm1[256];
  int t = threadIdx.x;
  float s0=0.f, s1=0.f;
  for (int i=blockIdx.x*256+t; i<VOL; i+=256*256){
    float2 v = make_float2(d_bb[i].x - d_Ap[i].x, d_bb[i].y - d_Ap[i].y);
    d_rr[i]=v; d_pp[i]=v;
    s0 += v.x*v.x; s1 += v.y*v.y;
  }
  sm0[t]=s0; sm1[t]=s1; __syncthreads();
  for (int st=128; st>0; st>>=1){ if (t<st){ sm0[t]+=sm0[t+st]; sm1[t]+=sm1[t+st]; } __syncthreads(); }
  if (t==0){ part[blockIdx.x]=sm0[0]; part[1024+blockIdx.x]=sm1[0]; }
}

__global__ __launch_bounds__(256) void k_update1(float* __restrict__ part){
  __shared__ float sm0[256], sm1[256];
  int t = threadIdx.x;
  float a0 = d_rs[0] / (d_pAp[0] + EPSI);
  float a1 = d_rs[1] / (d_pAp[1] + EPSI);
  float s0=0.f, s1=0.f;
  for (int i=blockIdx.x*256+t; i<VOL; i+=256*256){
    float2 p = d_pp[i], ap = d_Ap[i], xk = d_xk[i], r = d_rr[i];
    xk.x += a0*p.x;  xk.y += a1*p.y;  d_xk[i]=xk;
    r.x  -= a0*ap.x; r.y  -= a1*ap.y; d_rr[i]=r;
    s0 += r.x*r.x;   s1 += r.y*r.y;
  }
  sm0[t]=s0; sm1[t]=s1; __syncthreads();
  for (int st=128; st>0; st>>=1){ if (t<st){ sm0[t]+=sm0[t+st]; sm1[t]+=sm1[t+st]; } __syncthreads(); }
  if (t==0){ part[blockIdx.x]=sm0[0]; part[1024+blockIdx.x]=sm1[0]; }
}

__global__ __launch_bounds__(256) void k_update2(){
  float b0 = d_rsn[0] / (d_rs[0] + EPSI);
  float b1 = d_rsn[1] / (d_rs[1] + EPSI);
  for (int i=blockIdx.x*256+threadIdx.x; i<VOL; i+=256*256){
    float2 r = d_rr[i], p = d_pp[i];
    d_pp[i] = make_float2(r.x + b0*p.x, r.y + b1*p.y);
  }
}

__global__ void k_rscopy(){
  if (threadIdx.x < NB) d_rs[threadIdx.x] = d_rsn[threadIdx.x];
}

__global__ __launch_bounds__(256) void k_unpack(float* __restrict__ out){
  int i = blockIdx.x*256 + threadIdx.x;
  float2 v = d_xk[i];
  out[i] = v.x;
  out[VOL+i] = v.y;
}

// ---------------------------------------------------------------------------
// Host side
// ---------------------------------------------------------------------------
static void applyA(const float2* vin, float2* vout, float* pPart,
                   float2* pC0, float2* pTmp, const float* pSe, const uchar2* pM8){
  k_fwdz   <<<dim3(1024,1), 256>>>(vin, 0, pC0);
  k_passy<1><<<dim3(1024,1), 256>>>(pC0, 1.f);
  k_spreadx<<<2048, 128>>>(pC0, pSe, pTmp);
  k_passy<-1><<<dim3(1024,NR), 256>>>(pTmp, INV128);
  k_zfuse  <<<dim3(1024,NR), 256>>>(pTmp, pM8);
  k_passy<1><<<dim3(1024,NR), 256>>>(pTmp, 1.f);
  k_gatherx<<<2048, 128>>>(pTmp, pSe, pC0);
  k_passy<-1><<<dim3(1024,1), 256>>>(pC0, INV128);
  k_invz_ap<<<dim3(1024,1), 256>>>(pC0, vout, vin, LAMBDA, pPart);
}

extern "C" void kernel_launch(void* const* d_in, const int* in_sizes, int n_in,
                              void* d_out, int out_size){
  const float* x      = (const float*)d_in[0];   // [B,V]
  const float* x1     = (const float*)d_in[1];   // [B,V,R]
  const float* x3     = (const float*)d_in[2];   // [B,V]
  const float* init_x = (const float*)d_in[3];   // [B,V]
  const float* smv    = (const float*)d_in[4];   // [R,V]
  float* out = (float*)d_out;

  float2 *pC0, *pTmp, *pB, *pXk, *pR, *pP, *pAp;
  float *pSe, *pRs, *pPAp, *pRsn, *pPart;
  uchar2 *pM8;
  cudaGetSymbolAddress((void**)&pC0,  d_C0);
  cudaGetSymbolAddress((void**)&pTmp, d_tmp);
  cudaGetSymbolAddress((void**)&pSe,  d_Se);
  cudaGetSymbolAddress((void**)&pM8,  d_m8);
  cudaGetSymbolAddress((void**)&pB,   d_bb);
  cudaGetSymbolAddress((void**)&pXk,  d_xk);
  cudaGetSymbolAddress((void**)&pR,   d_rr);
  cudaGetSymbolAddress((void**)&pP,   d_pp);
  cudaGetSymbolAddress((void**)&pAp,  d_Ap);
  cudaGetSymbolAddress((void**)&pRs,  d_rs);
  cudaGetSymbolAddress((void**)&pPAp, d_pAp);
  cudaGetSymbolAddress((void**)&pRsn, d_rsn);
  cudaGetSymbolAddress((void**)&pPart,d_part);

  k_initW <<<1,128>>>();
  k_prep  <<<VOL/256, 256>>>(x, x1, x3, init_x);
  k_prepSe<<<dim3(VOL/256, NR), 256>>>(smv);

  // b = smv_adj( m * (w3 * x) )   -- wx packed is sitting in d_rr
  k_fwdz   <<<dim3(1024,NR), 256>>>(pR, pM8, pTmp);
  k_passy<1><<<dim3(1024,NR), 256>>>(pTmp, 1.f);
  k_gatherx<<<2048, 128>>>(pTmp, pSe, pC0);
  k_passy<-1><<<dim3(1024,1), 256>>>(pC0, INV128);
  k_invz_ap<<<dim3(1024,1), 256>>>(pC0, pB, 0, 0.f, 0);

  // r0 = b - A(x0); p = r0; rs = <r0,r0>
  applyA(pXk, pAp, 0, pC0, pTmp, pSe, pM8);
  k_init_r<<<256, 256>>>(pPart);
  k_fin<<<NB, 256>>>(pPart, pRs, 256);

  for (int it=0; it<NITER; ++it){
    applyA(pP, pAp, pPart, pC0, pTmp, pSe, pM8);
    k_fin<<<NB, 256>>>(pPart, pPAp, 1024);
    k_update1<<<256, 256>>>(pPart);
    k_fin<<<NB, 256>>>(pPart, pRsn, 256);
    k_update2<<<256, 256>>>();
    k_rscopy<<<1, 32>>>();
  }

  k_unpack<<<VOL/256, 256>>>(out);
}